// round 2
// baseline (speedup 1.0000x reference)
#include <cuda_runtime.h>
#include <cuda_bf16.h>
#include <math.h>

// Problem constants
#define Bc   64
#define Lc   2048
#define Dc   128
#define Hc   4
#define Ac   128
#define Mc   16
#define Vc   100000
#define NNZc 262144
#define HDc  32
#define GAMMAc 0.3
#define BETAc  1.0

// ---------------- scratch (static __device__, no allocation) ----------------
__device__ __align__(16) float  g_sigT[(size_t)Vc * Mc];   // sigmoid(phi) transposed: [v][m]
__device__ __align__(16) float  g_PhiP[Mc * Ac];
__device__ double g_sizeP[Mc];
__device__ __align__(16) float  g_PhiQ[Bc * Ac];
__device__ double g_psum[Bc * Mc];           // sum_{i in seg b} p[m, id_i]
__device__ __align__(16) float  g_AQ[Bc * Ac];
__device__ __align__(16) float  g_BP[Mc * Ac];
__device__ __align__(16) float  g_Vp[Mc * HDc];
__device__ __align__(16) float  g_Z[Bc * HDc];
__device__ __align__(16) float  g_C[Bc * Dc * Hc];         // [b][d][h]

// ---------------- K0: zero accumulators ----------------
__global__ void k0_init() {
    int idx = blockIdx.x * blockDim.x + threadIdx.x;
    int stride = gridDim.x * blockDim.x;
    for (int i = idx; i < Mc * Ac; i += stride) g_PhiP[i] = 0.f;
    for (int i = idx; i < Bc * Ac; i += stride) g_PhiQ[i] = 0.f;
    for (int i = idx; i < Mc; i += stride) g_sizeP[i] = 0.0;
    for (int i = idx; i < Bc * Mc; i += stride) g_psum[i] = 0.0;
}

// ---------------- K1: vocab pass ----------------
// sig = sigmoid(phi_logits); write sigT[v][m]; PhiP = sig @ atom_emb; sizeP = sum sig.
__global__ void __launch_bounds__(512) k1_vocab(const float* __restrict__ phi_logits,
                                                const float* __restrict__ atom_emb) {
    __shared__ __align__(16) float  sSig[2][256];   // [buf][vv*16 + m]
    __shared__ __align__(16) float  sRed[16 * 128]; // cross-warp reduction buffer
    __shared__ double sSz[256];

    const int t = threadIdx.x;
    const int w = t >> 5, lane = t & 31;
    const int mS = t >> 4, vS = t & 15;    // staging roles (t < 256)

    float accM[16][4];
#pragma unroll
    for (int m = 0; m < 16; m++) { accM[m][0]=0.f; accM[m][1]=0.f; accM[m][2]=0.f; accM[m][3]=0.f; }
    double szAcc = 0.0;

    int bufi = 0;
    const int nTiles = Vc / 16;   // 6250 exactly
    for (int gt = blockIdx.x; gt < nTiles; gt += gridDim.x) {
        const int v0 = gt * 16;
        if (t < 256) {
            float x = phi_logits[(size_t)mS * Vc + v0 + vS];
            float s = 1.0f / (1.0f + __expf(-x));
            sSig[bufi][vS * 16 + mS] = s;
            szAcc += (double)s;
        }
        __syncthreads();
        if (t < 256) {
            // fully coalesced transposed write of sigT
            int m2 = t & 15, v2 = t >> 4;
            g_sigT[(size_t)(v0 + v2) * 16 + m2] = sSig[bufi][v2 * 16 + m2];
        }
        // main accumulation: warp w handles vocab row v0+w
        const float4 e = *reinterpret_cast<const float4*>(&atom_emb[(size_t)(v0 + w) * Ac + lane * 4]);
        const float* sg = &sSig[bufi][w * 16];
#pragma unroll
        for (int m = 0; m < 16; m++) {
            float s = sg[m];
            accM[m][0] = fmaf(s, e.x, accM[m][0]);
            accM[m][1] = fmaf(s, e.y, accM[m][1]);
            accM[m][2] = fmaf(s, e.z, accM[m][2]);
            accM[m][3] = fmaf(s, e.w, accM[m][3]);
        }
        bufi ^= 1;
    }

    // sizeP reduction (staging thread t owned m = t>>4)
    if (t < 256) sSz[t] = szAcc;
    __syncthreads();
    if (t < 16) {
        double s = 0.0;
#pragma unroll
        for (int j = 0; j < 16; j++) s += sSz[t * 16 + j];
        atomicAdd(&g_sizeP[t], s);
    }
    // PhiP reduction across the 16 warps, one m at a time
    for (int m = 0; m < 16; m++) {
        __syncthreads();
        float4* dst = reinterpret_cast<float4*>(&sRed[w * 128 + lane * 4]);
        *dst = make_float4(accM[m][0], accM[m][1], accM[m][2], accM[m][3]);
        __syncthreads();
        if (t < 128) {
            float s = 0.f;
#pragma unroll
            for (int w2 = 0; w2 < 16; w2++) s += sRed[w2 * 128 + t];
            atomicAdd(&g_PhiP[m * Ac + t], s);
        }
    }
}

// ---------------- K2: nnz gather pass ----------------
// PhiQ[b] = sum of atom_emb rows in segment b; psum[b][m] = sum of sigT rows.
#define K2_CHUNK 512
__global__ void __launch_bounds__(128) k2_nnz(const int* __restrict__ qids,
                                              const int* __restrict__ qoffs,
                                              const float* __restrict__ atom_emb) {
    __shared__ int sOffs[Bc + 1];
    __shared__ int sIds[K2_CHUNK];
    const int t = threadIdx.x;
    for (int i = t; i < Bc + 1; i += 128) sOffs[i] = qoffs[i];
    const int i0 = blockIdx.x * K2_CHUNK;
    for (int i = t; i < K2_CHUNK; i += 128) sIds[i] = qids[i0 + i];
    __syncthreads();

    // first segment with offs[seg+1] > i0
    int lo = 0, hi = Bc - 1;
    while (lo < hi) { int mid = (lo + hi) >> 1; if (sOffs[mid + 1] <= i0) lo = mid + 1; else hi = mid; }
    int seg = lo;
    int nxt = sOffs[seg + 1];

    float accQ = 0.f;
    double accP = 0.0;
    bool dirty = false;
    const int iend = i0 + K2_CHUNK;
    int i = i0;
    while (i < iend) {
        if (i >= nxt) {
            if (dirty) {
                atomicAdd(&g_PhiQ[seg * Ac + t], accQ);
                if (t < 16) atomicAdd(&g_psum[seg * 16 + t], accP);
                accQ = 0.f; accP = 0.0; dirty = false;
            }
            do { seg++; nxt = sOffs[seg + 1]; } while (i >= nxt);
        }
        int lim = nxt < iend ? nxt : iend;
        int cnt = lim - i;
        int base = i - i0;
        dirty = true;
        int k = 0;
        for (; k + 4 <= cnt; k += 4) {
            int id0 = sIds[base + k + 0], id1 = sIds[base + k + 1];
            int id2 = sIds[base + k + 2], id3 = sIds[base + k + 3];
            float a0 = atom_emb[(size_t)id0 * Ac + t];
            float a1 = atom_emb[(size_t)id1 * Ac + t];
            float a2 = atom_emb[(size_t)id2 * Ac + t];
            float a3 = atom_emb[(size_t)id3 * Ac + t];
            accQ += (a0 + a1) + (a2 + a3);
            if (t < 16) {
                double s0 = (double)g_sigT[(size_t)id0 * 16 + t];
                double s1 = (double)g_sigT[(size_t)id1 * 16 + t];
                double s2 = (double)g_sigT[(size_t)id2 * 16 + t];
                double s3 = (double)g_sigT[(size_t)id3 * 16 + t];
                accP += (s0 + s1) + (s2 + s3);
            }
        }
        for (; k < cnt; k++) {
            int id = sIds[base + k];
            accQ += atom_emb[(size_t)id * Ac + t];
            if (t < 16) accP += (double)g_sigT[(size_t)id * 16 + t];
        }
        i = lim;
    }
    if (dirty) {
        atomicAdd(&g_PhiQ[seg * Ac + t], accQ);
        if (t < 16) atomicAdd(&g_psum[seg * 16 + t], accP);
    }
}

// ---------------- K3a: AQ = PhiQ @ W_A.T ; BP = PhiP @ W_B.T ; Vp = PhiP @ W_val.T + b_val ----
__global__ void __launch_bounds__(128) k3a(const float* __restrict__ W_A,
                                           const float* __restrict__ W_B,
                                           const float* __restrict__ W_val,
                                           const float* __restrict__ b_val) {
    __shared__ float sv[Ac];
    const int t = threadIdx.x;
    if (blockIdx.x < Bc) {
        int b = blockIdx.x;
        sv[t] = g_PhiQ[b * Ac + t];
        __syncthreads();
        float acc = 0.f;
        const float* wr = &W_A[t * Ac];
#pragma unroll 8
        for (int a = 0; a < Ac; a += 4) {
            float4 w4 = *reinterpret_cast<const float4*>(&wr[a]);
            acc += w4.x * sv[a] + w4.y * sv[a + 1] + w4.z * sv[a + 2] + w4.w * sv[a + 3];
        }
        g_AQ[b * Ac + t] = acc;
    } else {
        int m = blockIdx.x - Bc;
        sv[t] = g_PhiP[m * Ac + t];
        __syncthreads();
        float acc = 0.f;
        const float* wr = &W_B[t * Ac];
#pragma unroll 8
        for (int a = 0; a < Ac; a += 4) {
            float4 w4 = *reinterpret_cast<const float4*>(&wr[a]);
            acc += w4.x * sv[a] + w4.y * sv[a + 1] + w4.z * sv[a + 2] + w4.w * sv[a + 3];
        }
        g_BP[m * Ac + t] = acc;
        if (t < HDc) {
            float a2 = 0.f;
            const float* wv = &W_val[t * Ac];
#pragma unroll 8
            for (int a = 0; a < Ac; a++) a2 += wv[a] * sv[a];
            g_Vp[m * HDc + t] = a2 + b_val[t];
        }
    }
}

// ---------------- K3b: scores (fp64) -> softmax -> Z ----------------
__global__ void __launch_bounds__(1024) k3b(const int* __restrict__ qoffs,
                                            const float* __restrict__ size_w) {
    __shared__ float sAttn[Bc * Mc];
    const int t = threadIdx.x;            // t = b*16 + m
    const int b = t >> 4, m = t & 15;
    float dotv = 0.f;
    const float* aq = &g_AQ[b * Ac];
    const float* bp = &g_BP[m * Ac];
#pragma unroll 8
    for (int i = 0; i < Ac; i++) dotv += aq[i] * bp[i];

    double szQ = (double)(qoffs[b + 1] - qoffs[b]);
    double szP = g_sizeP[m];
    double delta = szQ + szP - 2.0 * g_psum[b * 16 + m];
    double score = -GAMMAc * delta + BETAc * (double)dotv
                 + (double)size_w[0] * szQ + (double)size_w[1] * szP;
    // softmax within 16-lane groups (TAU = 1)
    double mx = score;
#pragma unroll
    for (int k = 8; k; k >>= 1) mx = fmax(mx, __shfl_xor_sync(0xffffffffu, mx, k));
    double e = exp(score - mx);
    double ssum = e;
#pragma unroll
    for (int k = 8; k; k >>= 1) ssum += __shfl_xor_sync(0xffffffffu, ssum, k);
    sAttn[t] = (float)(e / ssum);
    __syncthreads();
    // Z = attn @ Vp  (64x32)
    for (int o = t; o < Bc * HDc; o += 1024) {
        int bb = o >> 5, hd = o & 31;
        float z = 0.f;
#pragma unroll
        for (int mm = 0; mm < 16; mm++) z += sAttn[bb * 16 + mm] * g_Vp[mm * HDc + hd];
        g_Z[o] = z;
    }
}

// ---------------- K4: C[b][d][h] = sum_j W_out[d][h*32+j] * Z[b][j] ----------------
__global__ void __launch_bounds__(128) k4_makeC(const float* __restrict__ W_out) {
    __shared__ float sz[HDc];
    const int b = blockIdx.x, t = threadIdx.x;
    if (t < HDc) sz[t] = g_Z[b * HDc + t];
    __syncthreads();
#pragma unroll
    for (int h = 0; h < Hc; h++) {
        float acc = 0.f;
        const float* wr = &W_out[t * Dc + h * HDc];
#pragma unroll 8
        for (int j = 0; j < HDc; j++) acc += wr[j] * sz[j];
        g_C[(b * Dc + t) * Hc + h] = acc;
    }
}

// ---------------- K5: token pass: gates softmax + out = gates . C + b_out ----------------
__global__ void __launch_bounds__(256) k5_tokens(const float* __restrict__ ts,
                                                 const float* __restrict__ W_gate,
                                                 const float* __restrict__ b_gate,
                                                 const float* __restrict__ b_out,
                                                 float* __restrict__ out) {
    const int t = threadIdx.x, w = t >> 5, lane = t & 31;
    const int b = blockIdx.x >> 4, part = blockIdx.x & 15;

    float4 wg[4];
#pragma unroll
    for (int h = 0; h < 4; h++) wg[h] = *reinterpret_cast<const float4*>(&W_gate[h * Dc + lane * 4]);
    float bg0 = b_gate[0], bg1 = b_gate[1], bg2 = b_gate[2], bg3 = b_gate[3];
    const float4 bo = *reinterpret_cast<const float4*>(&b_out[lane * 4]);
    float4 c[4];
#pragma unroll
    for (int j = 0; j < 4; j++) c[j] = *reinterpret_cast<const float4*>(&g_C[(b * Dc + lane * 4 + j) * Hc]);

    const float* xb = ts + (size_t)b * Lc * Dc;
    float* ob = out + (size_t)b * Lc * Dc;
    const int l0 = part * 128 + w * 16;
#pragma unroll 2
    for (int k = 0; k < 16; k++) {
        const int l = l0 + k;
        const float4 x = *reinterpret_cast<const float4*>(&xb[l * Dc + lane * 4]);
        float p0 = x.x * wg[0].x + x.y * wg[0].y + x.z * wg[0].z + x.w * wg[0].w;
        float p1 = x.x * wg[1].x + x.y * wg[1].y + x.z * wg[1].z + x.w * wg[1].w;
        float p2 = x.x * wg[2].x + x.y * wg[2].y + x.z * wg[2].z + x.w * wg[2].w;
        float p3 = x.x * wg[3].x + x.y * wg[3].y + x.z * wg[3].z + x.w * wg[3].w;
#pragma unroll
        for (int s = 16; s; s >>= 1) {
            p0 += __shfl_xor_sync(0xffffffffu, p0, s);
            p1 += __shfl_xor_sync(0xffffffffu, p1, s);
            p2 += __shfl_xor_sync(0xffffffffu, p2, s);
            p3 += __shfl_xor_sync(0xffffffffu, p3, s);
        }
        p0 += bg0; p1 += bg1; p2 += bg2; p3 += bg3;
        float mx = fmaxf(fmaxf(p0, p1), fmaxf(p2, p3));
        float e0 = __expf(p0 - mx), e1 = __expf(p1 - mx), e2 = __expf(p2 - mx), e3 = __expf(p3 - mx);
        float inv = 1.f / (e0 + e1 + e2 + e3);
        e0 *= inv; e1 *= inv; e2 *= inv; e3 *= inv;
        float4 o;
        o.x = bo.x + e0 * c[0].x + e1 * c[0].y + e2 * c[0].z + e3 * c[0].w;
        o.y = bo.y + e0 * c[1].x + e1 * c[1].y + e2 * c[1].z + e3 * c[1].w;
        o.z = bo.z + e0 * c[2].x + e1 * c[2].y + e2 * c[2].z + e3 * c[2].w;
        o.w = bo.w + e0 * c[3].x + e1 * c[3].y + e2 * c[3].z + e3 * c[3].w;
        *reinterpret_cast<float4*>(&ob[l * Dc + lane * 4]) = o;
    }
}

// ---------------- launcher ----------------
extern "C" void kernel_launch(void* const* d_in, const int* in_sizes, int n_in,
                              void* d_out, int out_size) {
    const float* token_states = (const float*)d_in[0];
    const int*   query_ids    = (const int*)d_in[1];
    const int*   query_offs   = (const int*)d_in[2];
    const float* atom_emb     = (const float*)d_in[3];
    const float* phi_logits   = (const float*)d_in[4];
    const float* W_A          = (const float*)d_in[5];
    const float* W_B          = (const float*)d_in[6];
    const float* W_val        = (const float*)d_in[7];
    const float* b_val        = (const float*)d_in[8];
    const float* W_gate       = (const float*)d_in[9];
    const float* b_gate       = (const float*)d_in[10];
    const float* W_out        = (const float*)d_in[11];
    const float* b_out        = (const float*)d_in[12];
    const float* size_w       = (const float*)d_in[13];
    float* out = (float*)d_out;

    k0_init<<<16, 256>>>();
    k1_vocab<<<148, 512>>>(phi_logits, atom_emb);
    k2_nnz<<<NNZc / K2_CHUNK, 128>>>(query_ids, query_offs, atom_emb);
    k3a<<<Bc + Mc, 128>>>(W_A, W_B, W_val, b_val);
    k3b<<<1, 1024>>>(query_offs, size_w);
    k4_makeC<<<Bc, 128>>>(W_out);
    k5_tokens<<<Bc * 16, 256>>>(token_states, W_gate, b_gate, b_out, out);
}

// round 3
// speedup vs baseline: 1.5336x; 1.5336x over previous
#include <cuda_runtime.h>
#include <cuda_bf16.h>
#include <math.h>

// Problem constants
#define Bc   64
#define Lc   2048
#define Dc   128
#define Hc   4
#define Ac   128
#define Mc   16
#define Vc   100000
#define NNZc 262144
#define HDc  32
#define GAMMAc 0.3
#define BETAc  1.0

typedef unsigned long long ull;

#define FMA2(acc, a, b) asm("fma.rn.f32x2 %0, %1, %2, %0;" : "+l"(acc) : "l"(a), "l"(b))
__device__ __forceinline__ ull pack2(float x, float y) {
    ull d; asm("mov.b64 %0, {%1, %2};" : "=l"(d) : "f"(x), "f"(y)); return d;
}
__device__ __forceinline__ float2 unpack2(ull v) {
    float2 r; asm("mov.b64 {%0, %1}, %2;" : "=f"(r.x), "=f"(r.y) : "l"(v)); return r;
}

// ---------------- scratch (static __device__, no allocation) ----------------
__device__ __align__(16) float  g_sigT[(size_t)Vc * Mc];   // sigmoid(phi) transposed: [v][m]
__device__ __align__(16) float  g_PhiP[Mc * Ac];
__device__ double g_sizeP[Mc];
__device__ __align__(16) float  g_PhiQ[Bc * Ac];
__device__ double g_psum[Bc * Mc];
__device__ __align__(16) float  g_AQ[Bc * Ac];
__device__ __align__(16) float  g_BP[Mc * Ac];
__device__ __align__(16) float  g_Vp[Mc * HDc];
__device__ __align__(16) float  g_Z[Bc * HDc];
__device__ __align__(16) float  g_C[Bc * Dc * Hc];         // [b][d][h]

// ---------------- K0: zero accumulators ----------------
__global__ void k0_init() {
    int idx = blockIdx.x * blockDim.x + threadIdx.x;
    int stride = gridDim.x * blockDim.x;
    for (int i = idx; i < Mc * Ac; i += stride) g_PhiP[i] = 0.f;
    for (int i = idx; i < Bc * Ac; i += stride) g_PhiQ[i] = 0.f;
    for (int i = idx; i < Mc; i += stride) g_sizeP[i] = 0.0;
    for (int i = idx; i < Bc * Mc; i += stride) g_psum[i] = 0.0;
}

// ---------------- K1: vocab pass ----------------
// Tile = 32 vocab rows. 512 threads: staging role (m=t>>5, v=t&31), compute role
// (warp w owns rows v0+w and v0+w+16). FFMA2 packed over m-pairs; software
// pipelined: next tile's phi + atom_emb rows are loaded during current compute.
#define SSTR 18   // smem row stride (even -> 8B-aligned pair loads)
__global__ void __launch_bounds__(512) k1_vocab(const float* __restrict__ phi_logits,
                                                const float* __restrict__ atom_emb) {
    __shared__ __align__(16) float sS[2][32 * SSTR];
    __shared__ __align__(16) float sRed[16 * 128];

    const int t = threadIdx.x;
    const int w = t >> 5, lane = t & 31;
    const int mS = t >> 5, vS = t & 31;      // staging role

    ull acc2[8][4];
#pragma unroll
    for (int mp = 0; mp < 8; mp++)
#pragma unroll
        for (int c = 0; c < 4; c++) acc2[mp][c] = pack2(0.f, 0.f);
    double szAcc = 0.0;

    const int nTiles = Vc / 32;   // 3125
    int gt = blockIdx.x;
    if (gt >= nTiles) return;     // (never for grid 148)

    // prologue: stage tile gt into buf 0, prefetch its e rows
    {
        float x = phi_logits[(size_t)mS * Vc + gt * 32 + vS];
        float s = 1.0f / (1.0f + __expf(-x));
        sS[0][vS * SSTR + mS] = s;
        szAcc += (double)s;
    }
    float4 eA = *reinterpret_cast<const float4*>(&atom_emb[((size_t)gt * 32 + w) * Ac + lane * 4]);
    float4 eB = *reinterpret_cast<const float4*>(&atom_emb[((size_t)gt * 32 + w + 16) * Ac + lane * 4]);
    __syncthreads();

    int cur = 0;
    for (; gt < nTiles; gt += gridDim.x) {
        const int gtn = gt + gridDim.x;
        const bool has = gtn < nTiles;
        float xn = 0.f; float4 eAn, eBn;
        if (has) {
            xn  = phi_logits[(size_t)mS * Vc + gtn * 32 + vS];
            eAn = *reinterpret_cast<const float4*>(&atom_emb[((size_t)gtn * 32 + w) * Ac + lane * 4]);
            eBn = *reinterpret_cast<const float4*>(&atom_emb[((size_t)gtn * 32 + w + 16) * Ac + lane * 4]);
        }
        // sigT writeout for current tile (reads other threads' staged values; synced)
        {
            int v2 = t >> 4, m2 = t & 15;
            g_sigT[((size_t)gt * 32 + v2) * 16 + m2] = sS[cur][v2 * SSTR + m2];
        }
        // compute: acc2[mp][c] += (s_{2mp}, s_{2mp+1}) * (e_c, e_c) for both rows
        {
            ull eDA[4], eDB[4];
            eDA[0] = pack2(eA.x, eA.x); eDA[1] = pack2(eA.y, eA.y);
            eDA[2] = pack2(eA.z, eA.z); eDA[3] = pack2(eA.w, eA.w);
            eDB[0] = pack2(eB.x, eB.x); eDB[1] = pack2(eB.y, eB.y);
            eDB[2] = pack2(eB.z, eB.z); eDB[3] = pack2(eB.w, eB.w);
            const ull* spA = reinterpret_cast<const ull*>(&sS[cur][w * SSTR]);
            const ull* spB = reinterpret_cast<const ull*>(&sS[cur][(w + 16) * SSTR]);
#pragma unroll
            for (int mp = 0; mp < 8; mp++) {
                ull sA2 = spA[mp];
                ull sB2 = spB[mp];
#pragma unroll
                for (int c = 0; c < 4; c++) {
                    FMA2(acc2[mp][c], sA2, eDA[c]);
                    FMA2(acc2[mp][c], sB2, eDB[c]);
                }
            }
        }
        // stage next tile
        if (has) {
            float s = 1.0f / (1.0f + __expf(-xn));
            sS[cur ^ 1][vS * SSTR + mS] = s;
            szAcc += (double)s;
        }
        __syncthreads();
        eA = eAn; eB = eBn; cur ^= 1;
    }

    // sizeP: warp w's 32 lanes hold m=w contributions
    {
        double s = szAcc;
#pragma unroll
        for (int k = 16; k; k >>= 1) s += __shfl_xor_sync(0xffffffffu, s, k);
        if (lane == 0) atomicAdd(&g_sizeP[w], s);
    }
    // PhiP reduction across 16 warps, one m at a time
    for (int m = 0; m < 16; m++) {
        const int mp = m >> 1, hi = m & 1;
        __syncthreads();
        float4 v;
        float2 u0 = unpack2(acc2[mp][0]);
        float2 u1 = unpack2(acc2[mp][1]);
        float2 u2 = unpack2(acc2[mp][2]);
        float2 u3 = unpack2(acc2[mp][3]);
        v.x = hi ? u0.y : u0.x; v.y = hi ? u1.y : u1.x;
        v.z = hi ? u2.y : u2.x; v.w = hi ? u3.y : u3.x;
        *reinterpret_cast<float4*>(&sRed[w * 128 + lane * 4]) = v;
        __syncthreads();
        if (t < 128) {
            float s = 0.f;
#pragma unroll
            for (int w2 = 0; w2 < 16; w2++) s += sRed[w2 * 128 + t];
            atomicAdd(&g_PhiP[m * Ac + t], s);
        }
    }
}

// ---------------- K2: nnz gather pass ----------------
#define K2_CHUNK 128
__global__ void __launch_bounds__(128) k2_nnz(const int* __restrict__ qids,
                                              const int* __restrict__ qoffs,
                                              const float* __restrict__ atom_emb) {
    __shared__ int sOffs[Bc + 1];
    __shared__ int sIds[K2_CHUNK];
    const int t = threadIdx.x;
    if (t < Bc + 1) sOffs[t] = qoffs[t];
    const int i0 = blockIdx.x * K2_CHUNK;
    sIds[t] = qids[i0 + t];
    __syncthreads();

    int lo = 0, hi = Bc - 1;
    while (lo < hi) { int mid = (lo + hi) >> 1; if (sOffs[mid + 1] <= i0) lo = mid + 1; else hi = mid; }
    int seg = lo;
    int nxt = sOffs[seg + 1];

    float accQ = 0.f;
    double accP = 0.0;
    bool dirty = false;
    const int iend = i0 + K2_CHUNK;
    int i = i0;
    while (i < iend) {
        if (i >= nxt) {
            if (dirty) {
                atomicAdd(&g_PhiQ[seg * Ac + t], accQ);
                if (t < 16) atomicAdd(&g_psum[seg * 16 + t], accP);
                accQ = 0.f; accP = 0.0; dirty = false;
            }
            do { seg++; nxt = sOffs[seg + 1]; } while (i >= nxt);
        }
        int lim = nxt < iend ? nxt : iend;
        int cnt = lim - i;
        int base = i - i0;
        dirty = true;
        int k = 0;
        for (; k + 8 <= cnt; k += 8) {
            int id[8];
#pragma unroll
            for (int j = 0; j < 8; j++) id[j] = sIds[base + k + j];
            float a[8];
#pragma unroll
            for (int j = 0; j < 8; j++) a[j] = atom_emb[(size_t)id[j] * Ac + t];
            accQ += ((a[0] + a[1]) + (a[2] + a[3])) + ((a[4] + a[5]) + (a[6] + a[7]));
            if (t < 16) {
                double s = 0.0;
#pragma unroll
                for (int j = 0; j < 8; j++) s += (double)g_sigT[(size_t)id[j] * 16 + t];
                accP += s;
            }
        }
        for (; k < cnt; k++) {
            int id = sIds[base + k];
            accQ += atom_emb[(size_t)id * Ac + t];
            if (t < 16) accP += (double)g_sigT[(size_t)id * 16 + t];
        }
        i = lim;
    }
    if (dirty) {
        atomicAdd(&g_PhiQ[seg * Ac + t], accQ);
        if (t < 16) atomicAdd(&g_psum[seg * 16 + t], accP);
    }
}

// ---------------- K3a: AQ = PhiQ @ W_A.T ; BP = PhiP @ W_B.T ; Vp = PhiP @ W_val.T + b_val ----
__global__ void __launch_bounds__(128) k3a(const float* __restrict__ W_A,
                                           const float* __restrict__ W_B,
                                           const float* __restrict__ W_val,
                                           const float* __restrict__ b_val) {
    __shared__ float sv[Ac];
    const int t = threadIdx.x;
    if (blockIdx.x < Bc) {
        int b = blockIdx.x;
        sv[t] = g_PhiQ[b * Ac + t];
        __syncthreads();
        float acc = 0.f;
        const float* wr = &W_A[t * Ac];
#pragma unroll 16
        for (int a = 0; a < Ac; a += 4) {
            float4 w4 = *reinterpret_cast<const float4*>(&wr[a]);
            acc += w4.x * sv[a] + w4.y * sv[a + 1] + w4.z * sv[a + 2] + w4.w * sv[a + 3];
        }
        g_AQ[b * Ac + t] = acc;
    } else {
        int m = blockIdx.x - Bc;
        sv[t] = g_PhiP[m * Ac + t];
        __syncthreads();
        float acc = 0.f;
        const float* wr = &W_B[t * Ac];
#pragma unroll 16
        for (int a = 0; a < Ac; a += 4) {
            float4 w4 = *reinterpret_cast<const float4*>(&wr[a]);
            acc += w4.x * sv[a] + w4.y * sv[a + 1] + w4.z * sv[a + 2] + w4.w * sv[a + 3];
        }
        g_BP[m * Ac + t] = acc;
        if (t < HDc) {
            float a2 = 0.f;
            const float* wv = &W_val[t * Ac];
#pragma unroll 16
            for (int a = 0; a < Ac; a++) a2 += wv[a] * sv[a];
            g_Vp[m * HDc + t] = a2 + b_val[t];
        }
    }
}

// ---------------- K3b: scores (fp64) -> softmax -> Z ----------------
__global__ void __launch_bounds__(1024) k3b(const int* __restrict__ qoffs,
                                            const float* __restrict__ size_w) {
    __shared__ float sAttn[Bc * Mc];
    const int t = threadIdx.x;            // t = b*16 + m
    const int b = t >> 4, m = t & 15;
    float dotv = 0.f;
    const float4* aq = reinterpret_cast<const float4*>(&g_AQ[b * Ac]);
    const float4* bp = reinterpret_cast<const float4*>(&g_BP[m * Ac]);
#pragma unroll 8
    for (int i = 0; i < Ac / 4; i++) {
        float4 a4 = aq[i], b4 = bp[i];
        dotv += a4.x * b4.x + a4.y * b4.y + a4.z * b4.z + a4.w * b4.w;
    }

    double szQ = (double)(qoffs[b + 1] - qoffs[b]);
    double szP = g_sizeP[m];
    double delta = szQ + szP - 2.0 * g_psum[b * 16 + m];
    double score = -GAMMAc * delta + BETAc * (double)dotv
                 + (double)size_w[0] * szQ + (double)size_w[1] * szP;
    double mx = score;
#pragma unroll
    for (int k = 8; k; k >>= 1) mx = fmax(mx, __shfl_xor_sync(0xffffffffu, mx, k));
    double e = exp(score - mx);
    double ssum = e;
#pragma unroll
    for (int k = 8; k; k >>= 1) ssum += __shfl_xor_sync(0xffffffffu, ssum, k);
    sAttn[t] = (float)(e / ssum);
    __syncthreads();
    for (int o = t; o < Bc * HDc; o += 1024) {
        int bb = o >> 5, hd = o & 31;
        float z = 0.f;
#pragma unroll
        for (int mm = 0; mm < 16; mm++) z += sAttn[bb * 16 + mm] * g_Vp[mm * HDc + hd];
        g_Z[o] = z;
    }
}

// ---------------- K4: C[b][d][h] = sum_j W_out[d][h*32+j] * Z[b][j] ----------------
__global__ void __launch_bounds__(128) k4_makeC(const float* __restrict__ W_out) {
    __shared__ float sz[HDc];
    const int b = blockIdx.x, t = threadIdx.x;
    if (t < HDc) sz[t] = g_Z[b * HDc + t];
    __syncthreads();
#pragma unroll
    for (int h = 0; h < Hc; h++) {
        float acc = 0.f;
        const float* wr = &W_out[t * Dc + h * HDc];
#pragma unroll 8
        for (int j = 0; j < HDc; j++) acc += wr[j] * sz[j];
        g_C[(b * Dc + t) * Hc + h] = acc;
    }
}

// ---------------- K5: token pass: gates softmax + out = gates . C + b_out ----------------
__global__ void __launch_bounds__(256) k5_tokens(const float* __restrict__ ts,
                                                 const float* __restrict__ W_gate,
                                                 const float* __restrict__ b_gate,
                                                 const float* __restrict__ b_out,
                                                 float* __restrict__ out) {
    const int t = threadIdx.x, w = t >> 5, lane = t & 31;
    const int b = blockIdx.x >> 4, part = blockIdx.x & 15;

    float4 wg[4];
#pragma unroll
    for (int h = 0; h < 4; h++) wg[h] = *reinterpret_cast<const float4*>(&W_gate[h * Dc + lane * 4]);
    float bg0 = b_gate[0], bg1 = b_gate[1], bg2 = b_gate[2], bg3 = b_gate[3];
    const float4 bo = *reinterpret_cast<const float4*>(&b_out[lane * 4]);
    float4 c[4];
#pragma unroll
    for (int j = 0; j < 4; j++) c[j] = *reinterpret_cast<const float4*>(&g_C[(b * Dc + lane * 4 + j) * Hc]);

    const float* xb = ts + (size_t)b * Lc * Dc;
    float* ob = out + (size_t)b * Lc * Dc;
    const int l0 = part * 128 + w * 16;
#pragma unroll 2
    for (int k = 0; k < 16; k++) {
        const int l = l0 + k;
        const float4 x = *reinterpret_cast<const float4*>(&xb[l * Dc + lane * 4]);
        float p0 = x.x * wg[0].x + x.y * wg[0].y + x.z * wg[0].z + x.w * wg[0].w;
        float p1 = x.x * wg[1].x + x.y * wg[1].y + x.z * wg[1].z + x.w * wg[1].w;
        float p2 = x.x * wg[2].x + x.y * wg[2].y + x.z * wg[2].z + x.w * wg[2].w;
        float p3 = x.x * wg[3].x + x.y * wg[3].y + x.z * wg[3].z + x.w * wg[3].w;
#pragma unroll
        for (int s = 16; s; s >>= 1) {
            p0 += __shfl_xor_sync(0xffffffffu, p0, s);
            p1 += __shfl_xor_sync(0xffffffffu, p1, s);
            p2 += __shfl_xor_sync(0xffffffffu, p2, s);
            p3 += __shfl_xor_sync(0xffffffffu, p3, s);
        }
        p0 += bg0; p1 += bg1; p2 += bg2; p3 += bg3;
        float mx = fmaxf(fmaxf(p0, p1), fmaxf(p2, p3));
        float e0 = __expf(p0 - mx), e1 = __expf(p1 - mx), e2 = __expf(p2 - mx), e3 = __expf(p3 - mx);
        float inv = 1.f / (e0 + e1 + e2 + e3);
        e0 *= inv; e1 *= inv; e2 *= inv; e3 *= inv;
        float4 o;
        o.x = bo.x + e0 * c[0].x + e1 * c[0].y + e2 * c[0].z + e3 * c[0].w;
        o.y = bo.y + e0 * c[1].x + e1 * c[1].y + e2 * c[1].z + e3 * c[1].w;
        o.z = bo.z + e0 * c[2].x + e1 * c[2].y + e2 * c[2].z + e3 * c[2].w;
        o.w = bo.w + e0 * c[3].x + e1 * c[3].y + e2 * c[3].z + e3 * c[3].w;
        *reinterpret_cast<float4*>(&ob[l * Dc + lane * 4]) = o;
    }
}

// ---------------- launcher ----------------
extern "C" void kernel_launch(void* const* d_in, const int* in_sizes, int n_in,
                              void* d_out, int out_size) {
    const float* token_states = (const float*)d_in[0];
    const int*   query_ids    = (const int*)d_in[1];
    const int*   query_offs   = (const int*)d_in[2];
    const float* atom_emb     = (const float*)d_in[3];
    const float* phi_logits   = (const float*)d_in[4];
    const float* W_A          = (const float*)d_in[5];
    const float* W_B          = (const float*)d_in[6];
    const float* W_val        = (const float*)d_in[7];
    const float* b_val        = (const float*)d_in[8];
    const float* W_gate       = (const float*)d_in[9];
    const float* b_gate       = (const float*)d_in[10];
    const float* W_out        = (const float*)d_in[11];
    const float* b_out        = (const float*)d_in[12];
    const float* size_w       = (const float*)d_in[13];
    float* out = (float*)d_out;

    k0_init<<<32, 256>>>();
    k1_vocab<<<148, 512>>>(phi_logits, atom_emb);
    k2_nnz<<<NNZc / K2_CHUNK, 128>>>(query_ids, query_offs, atom_emb);
    k3a<<<Bc + Mc, 128>>>(W_A, W_B, W_val, b_val);
    k3b<<<1, 1024>>>(query_offs, size_w);
    k4_makeC<<<Bc, 128>>>(W_out);
    k5_tokens<<<Bc * 16, 256>>>(token_states, W_gate, b_gate, b_out, out);
}